// round 5
// baseline (speedup 1.0000x reference)
#include <cuda_runtime.h>
#include <cstdint>

typedef unsigned long long u64;
typedef ulonglong2 u64x2;

#define HD   19      // hidden size
#define HP   10      // hidden pairs (padded to 20)
#define WPAD 12      // u64 per packed weight row (10 used; 96B = 16B-aligned)
#define DD   64      // input size
#define TPB  128
#define RPT  2       // batch rows per thread in k_main
#define RPB  (TPB * RPT)
#define BMAX 524288
#define NPART 4096   // pass1 grid

__device__ float g_partials[NPART];
__device__ u64   g_mapped[(size_t)BMAX * HP];   // packed mapped = x@Wi^T + bi

struct Tables {
    u64 Wr2[HD * WPAD];
    u64 Wo2[HD * WPAD];
    u64 bo2[HP];
    u64 bdt2[HP];      // packed dt/tau_dyn, pad lane = 0
};
__device__ Tables g_tab;
#define TAB_U64 ((int)(sizeof(Tables) / 8))

// ---------- packed f32x2 helpers (sm_103a) ----------
static __device__ __forceinline__ u64 pk2(float lo, float hi) {
    u64 r; asm("mov.b64 %0,{%1,%2};" : "=l"(r) : "f"(lo), "f"(hi)); return r;
}
static __device__ __forceinline__ void upk2(u64 v, float& lo, float& hi) {
    asm("mov.b64 {%0,%1},%2;" : "=f"(lo), "=f"(hi) : "l"(v));
}
static __device__ __forceinline__ u64 fma2(u64 a, u64 b, u64 c) {
    u64 d; asm("fma.rn.f32x2 %0,%1,%2,%3;" : "=l"(d) : "l"(a), "l"(b), "l"(c)); return d;
}
static __device__ __forceinline__ float tanha(float v) {
    float r; asm("tanh.approx.f32 %0,%1;" : "=f"(r) : "f"(v)); return r;
}

// ---------- kernel 1: |x| partials + mapped = x@Wi^T + bi ----------
__global__ void __launch_bounds__(TPB) k_pass1(
    const float* __restrict__ x, const float* __restrict__ Wi,
    const float* __restrict__ bi)
{
    __shared__ __align__(16) float sx[TPB * 68];    // padded x tile (34816 B)
    __shared__ __align__(16) u64  sWi[DD * WPAD];   // 6144 B
    __shared__ u64  sBi[HP];
    __shared__ float sred[TPB / 32];
    const int tid = threadIdx.x;

    // pack Wi: sWi[k*WPAD+jp] = (Wi[2jp][k], Wi[2jp+1][k])
    for (int i = tid; i < DD * HP; i += TPB) {
        int k = i / HP, jp = i % HP;
        float w0 = Wi[(2 * jp) * DD + k];
        float w1 = (2 * jp + 1 < HD) ? Wi[(2 * jp + 1) * DD + k] : 0.f;
        sWi[k * WPAD + jp] = pk2(w0, w1);
    }
    if (tid < HP) {
        float b0 = bi[2 * tid];
        float b1 = (2 * tid + 1 < HD) ? bi[2 * tid + 1] : 0.f;
        sBi[tid] = pk2(b0, b1);
    }
    // coalesced x tile load (128 rows x 64 floats, pad row to 17 float4)
    const float4* xg = (const float4*)(x + (size_t)blockIdx.x * (TPB * DD));
    float4* sx4 = (float4*)sx;
    for (int j = tid; j < TPB * (DD / 4); j += TPB) {
        int row = j >> 4, q = j & 15;
        sx4[row * 17 + q] = xg[j];
    }
    __syncthreads();

    // row -> registers
    float xv[DD];
    {
        const float4* rp = sx4 + tid * 17;
#pragma unroll
        for (int q = 0; q < 16; q++) {
            float4 v = rp[q];
            xv[4 * q] = v.x; xv[4 * q + 1] = v.y;
            xv[4 * q + 2] = v.z; xv[4 * q + 3] = v.w;
        }
    }
    // abs-sum reduction
    float s = 0.f;
#pragma unroll
    for (int k = 0; k < DD; k++) s += fabsf(xv[k]);
#pragma unroll
    for (int o = 16; o > 0; o >>= 1) s += __shfl_down_sync(0xffffffffu, s, o);
    if ((tid & 31) == 0) sred[tid >> 5] = s;

    // mapped
    u64 m[HP];
#pragma unroll
    for (int jp = 0; jp < HP; jp++) m[jp] = sBi[jp];
#pragma unroll 4
    for (int k = 0; k < DD; k++) {
        u64 xd = pk2(xv[k], xv[k]);
        const u64x2* w = (const u64x2*)&sWi[k * WPAD];
#pragma unroll
        for (int p = 0; p < 5; p++) {
            u64x2 ww = w[p];
            m[2 * p]     = fma2(xd, ww.x, m[2 * p]);
            m[2 * p + 1] = fma2(xd, ww.y, m[2 * p + 1]);
        }
    }
    __syncthreads();
    if (tid == 0) {
        float t = 0.f;
#pragma unroll
        for (int i = 0; i < TPB / 32; i++) t += sred[i];
        g_partials[blockIdx.x] = t;
    }
    // stage mapped, then coalesced u64 store
    u64* st = (u64*)sx;
#pragma unroll
    for (int p = 0; p < HP; p++) st[tid * HP + p] = m[p];
    __syncthreads();
    u64* gm = g_mapped + (size_t)blockIdx.x * (TPB * HP);
    for (int i = tid; i < TPB * HP; i += TPB) gm[i] = st[i];
}

// ---------- kernel 2: finish reduction + build packed tables ----------
__global__ void __launch_bounds__(256) k_prep(
    const float* __restrict__ Wr, const float* __restrict__ Wo,
    const float* __restrict__ bo, const float* __restrict__ tau,
    const float* __restrict__ ta, float invN)
{
    __shared__ float red[256];
    __shared__ float urg_s;
    int t = threadIdx.x;

    float s = 0.f;
    for (int i = t; i < NPART; i += 256) s += g_partials[i];
    red[t] = s;
    __syncthreads();
#pragma unroll
    for (int o = 128; o > 0; o >>= 1) {
        if (t < o) red[t] += red[t + o];
        __syncthreads();
    }
    if (t == 0) urg_s = fmaxf(red[0] * invN, 0.01f);
    __syncthreads();
    float urg = urg_s;

    for (int i = t; i < HD * HP; i += 256) {
        int k = i / HP, jp = i % HP;
        float r0 = Wr[(2 * jp) * HD + k];
        float r1 = (2 * jp + 1 < HD) ? Wr[(2 * jp + 1) * HD + k] : 0.f;
        g_tab.Wr2[k * WPAD + jp] = pk2(r0, r1);
        float o0 = Wo[(2 * jp) * HD + k];
        float o1 = (2 * jp + 1 < HD) ? Wo[(2 * jp + 1) * HD + k] : 0.f;
        g_tab.Wo2[k * WPAD + jp] = pk2(o0, o1);
    }
    if (t < HP) {
        float c0 = bo[2 * t];
        float c1 = (2 * t + 1 < HD) ? bo[2 * t + 1] : 0.f;
        g_tab.bo2[t] = pk2(c0, c1);

        float bd0, bd1 = 0.f;
        {
            float td = tau[2 * t] * (1.0f - ta[2 * t]) + ta[2 * t] / urg;
            td = fminf(fmaxf(td, 0.01f), 10.0f);
            bd0 = 0.01f / td;
        }
        if (2 * t + 1 < HD) {
            float td = tau[2 * t + 1] * (1.0f - ta[2 * t + 1]) + ta[2 * t + 1] / urg;
            td = fminf(fmaxf(td, 0.01f), 10.0f);
            bd1 = 0.01f / td;
        }
        g_tab.bdt2[t] = pk2(bd0, bd1);
    }
}

// ---------- kernel 3: recurrence + output, 2 rows/thread ----------
__global__ void __launch_bounds__(TPB)
k_main(const int* __restrict__ steps_p, float* __restrict__ out,
       float* __restrict__ hout)
{
    __shared__ __align__(16) u64 sm[4864];   // 38912 B
    const int tid = threadIdx.x;

    {   // tables -> [0,480), mapped tile -> [480, 3040)
        const u64* gt = (const u64*)&g_tab;
        for (int i = tid; i < TAB_U64; i += TPB) sm[i] = gt[i];
        const u64* gm = g_mapped + (size_t)blockIdx.x * (RPB * HP);
        for (int i = tid; i < RPB * HP; i += TPB) sm[480 + i] = gm[i];
    }
    __syncthreads();
    const u64* sWr = sm;                       // @0
    const u64* sWo = sWr + HD * WPAD;          // @228
    const u64* sBo = sWo + HD * WPAD;          // @456
    const u64* sBd = sBo + HP;                 // @466
    const u64* smap = sm + 480;

    const u64x2* mst0 = (const u64x2*)&smap[(size_t)tid * HP];
    const u64x2* mst1 = (const u64x2*)&smap[(size_t)(tid + TPB) * HP];

    u64 h0[HP], h1[HP], bb[HP];
    const u64 zero2 = pk2(0.f, 0.f);
    const u64 neg1  = pk2(-1.f, -1.f);
#pragma unroll
    for (int jp = 0; jp < HP; jp++) { h0[jp] = zero2; h1[jp] = zero2; bb[jp] = sBd[jp]; }

    const int steps = *steps_p;
    for (int s = 0; s < steps; s++) {
        u64 a0[HP], a1[HP];
#pragma unroll
        for (int p = 0; p < 5; p++) {
            u64x2 v0 = mst0[p]; a0[2 * p] = v0.x; a0[2 * p + 1] = v0.y;
            u64x2 v1 = mst1[p]; a1[2 * p] = v1.x; a1[2 * p + 1] = v1.y;
        }

#pragma unroll
        for (int kp = 0; kp < HP - 1; kp++) {      // k = 2kp, 2kp+1
            float e0, f0, e1, f1;
            upk2(h0[kp], e0, f0);
            upk2(h1[kp], e1, f1);
            u64 p00 = pk2(e0, e0), p01 = pk2(f0, f0);
            u64 p10 = pk2(e1, e1), p11 = pk2(f1, f1);
            const u64x2* wA = (const u64x2*)&sWr[(2 * kp) * WPAD];
            const u64x2* wB = (const u64x2*)&sWr[(2 * kp + 1) * WPAD];
#pragma unroll
            for (int p = 0; p < 5; p++) {
                u64x2 wa = wA[p];
                a0[2 * p]     = fma2(p00, wa.x, a0[2 * p]);
                a0[2 * p + 1] = fma2(p00, wa.y, a0[2 * p + 1]);
                a1[2 * p]     = fma2(p10, wa.x, a1[2 * p]);
                a1[2 * p + 1] = fma2(p10, wa.y, a1[2 * p + 1]);
            }
#pragma unroll
            for (int p = 0; p < 5; p++) {
                u64x2 wb = wB[p];
                a0[2 * p]     = fma2(p01, wb.x, a0[2 * p]);
                a0[2 * p + 1] = fma2(p01, wb.y, a0[2 * p + 1]);
                a1[2 * p]     = fma2(p11, wb.x, a1[2 * p]);
                a1[2 * p + 1] = fma2(p11, wb.y, a1[2 * p + 1]);
            }
        }
        {   // k = 18
            float e0, f0, e1, f1;
            upk2(h0[HP - 1], e0, f0);
            upk2(h1[HP - 1], e1, f1);
            u64 p0 = pk2(e0, e0), p1 = pk2(e1, e1);
            const u64x2* w = (const u64x2*)&sWr[18 * WPAD];
#pragma unroll
            for (int p = 0; p < 5; p++) {
                u64x2 ww = w[p];
                a0[2 * p]     = fma2(p0, ww.x, a0[2 * p]);
                a0[2 * p + 1] = fma2(p0, ww.y, a0[2 * p + 1]);
                a1[2 * p]     = fma2(p1, ww.x, a1[2 * p]);
                a1[2 * p + 1] = fma2(p1, ww.y, a1[2 * p + 1]);
            }
        }

        // h += b * (tanh(a) - h)
#pragma unroll
        for (int jp = 0; jp < HP; jp++) {
            float u, v;
            upk2(a0[jp], u, v);
            u64 act = pk2(tanha(u), tanha(v));
            u64 d = fma2(h0[jp], neg1, act);
            h0[jp] = fma2(bb[jp], d, h0[jp]);
            upk2(a1[jp], u, v);
            act = pk2(tanha(u), tanha(v));
            d = fma2(h1[jp], neg1, act);
            h1[jp] = fma2(bb[jp], d, h1[jp]);
        }
    }

    // ---- out = h @ Wo^T + bo ----
    u64 o0[HP], o1[HP];
#pragma unroll
    for (int jp = 0; jp < HP; jp++) { o0[jp] = sBo[jp]; o1[jp] = sBo[jp]; }
#pragma unroll
    for (int kp = 0; kp < HP; kp++) {
        float e0, f0, e1, f1;
        upk2(h0[kp], e0, f0);
        upk2(h1[kp], e1, f1);
        u64 p00 = pk2(e0, e0), p10 = pk2(e1, e1);
        const u64x2* wA = (const u64x2*)&sWo[(2 * kp) * WPAD];
#pragma unroll
        for (int p = 0; p < 5; p++) {
            u64x2 wa = wA[p];
            o0[2 * p]     = fma2(p00, wa.x, o0[2 * p]);
            o0[2 * p + 1] = fma2(p00, wa.y, o0[2 * p + 1]);
            o1[2 * p]     = fma2(p10, wa.x, o1[2 * p]);
            o1[2 * p + 1] = fma2(p10, wa.y, o1[2 * p + 1]);
        }
        if (kp < HP - 1) {
            u64 p01 = pk2(f0, f0), p11 = pk2(f1, f1);
            const u64x2* wB = (const u64x2*)&sWo[(2 * kp + 1) * WPAD];
#pragma unroll
            for (int p = 0; p < 5; p++) {
                u64x2 wb = wB[p];
                o0[2 * p]     = fma2(p01, wb.x, o0[2 * p]);
                o0[2 * p + 1] = fma2(p01, wb.y, o0[2 * p + 1]);
                o1[2 * p]     = fma2(p11, wb.x, o1[2 * p]);
                o1[2 * p + 1] = fma2(p11, wb.y, o1[2 * p + 1]);
            }
        }
    }

    // ---- stage outputs, coalesced float4 stores ----
    __syncthreads();
    float* f = (float*)sm;           // out: [0,4864) floats, h: [4864,9728)
    const int l0 = tid * HD;
    const int l1 = (tid + TPB) * HD;
#pragma unroll
    for (int jp = 0; jp < HP; jp++) {
        float lo, hi;
        upk2(o0[jp], lo, hi);
        f[l0 + 2 * jp] = lo;
        if (jp < HP - 1) f[l0 + 2 * jp + 1] = hi;
        upk2(o1[jp], lo, hi);
        f[l1 + 2 * jp] = lo;
        if (jp < HP - 1) f[l1 + 2 * jp + 1] = hi;
        upk2(h0[jp], lo, hi);
        f[4864 + l0 + 2 * jp] = lo;
        if (jp < HP - 1) f[4864 + l0 + 2 * jp + 1] = hi;
        upk2(h1[jp], lo, hi);
        f[4864 + l1 + 2 * jp] = lo;
        if (jp < HP - 1) f[4864 + l1 + 2 * jp + 1] = hi;
    }
    __syncthreads();

    const float4* f4o = (const float4*)f;
    const float4* f4h = (const float4*)(f + 4864);
    float4* go = (float4*)(out + (size_t)blockIdx.x * (RPB * HD));
    if (hout) {
        float4* gh = (float4*)(hout + (size_t)blockIdx.x * (RPB * HD));
        for (int i = tid; i < RPB * HD / 4; i += TPB) {
            go[i] = f4o[i];
            gh[i] = f4h[i];
        }
    } else {
        for (int i = tid; i < RPB * HD / 4; i += TPB) go[i] = f4o[i];
    }
}

extern "C" void kernel_launch(void* const* d_in, const int* in_sizes, int n_in,
                              void* d_out, int out_size) {
    const float* x   = (const float*)d_in[0];
    const float* Wi  = (const float*)d_in[1];
    const float* bi  = (const float*)d_in[2];
    const float* Wr  = (const float*)d_in[3];
    const float* Wo  = (const float*)d_in[4];
    const float* bo  = (const float*)d_in[5];
    const float* tau = (const float*)d_in[6];
    const float* ta  = (const float*)d_in[7];
    const int* steps = (const int*)d_in[8];

    const int nx = in_sizes[0];
    const int B  = nx / DD;

    float* out = (float*)d_out;
    long long bh = (long long)B * HD;
    float* hout = ((long long)out_size >= 2 * bh) ? (out + bh) : nullptr;

    k_pass1<<<B / TPB, TPB>>>(x, Wi, bi);
    k_prep<<<1, 256>>>(Wr, Wo, bo, tau, ta, 1.0f / (float)nx);
    k_main<<<B / RPB, TPB>>>(steps, out, hout);
}

// round 6
// speedup vs baseline: 1.1471x; 1.1471x over previous
#include <cuda_runtime.h>
#include <cstdint>

typedef unsigned long long u64;
typedef ulonglong2 u64x2;

#define HD   19      // hidden size
#define HP   10      // hidden pairs (padded to 20)
#define WPAD 12      // u64 per packed weight row (10 used; 96B, 16B-aligned)
#define DD   64      // input size
#define TPB  128
#define RPT  4       // batch rows per thread
#define RPB  (TPB * RPT)   // 512 rows per block
#define NPART 1024

__device__ float g_partials[NPART];

struct Tables {
    u64 Wi2[DD * WPAD];   // [k][jp]: (Wi[2jp][k], Wi[2jp+1][k])
    u64 Wr2[HD * WPAD];
    u64 Wo2[HD * WPAD];
    u64 bi2[HP];
    u64 bo2[HP];
    u64 bdt2[HP];         // packed dt/tau_dyn, pad lane = 0
};
__device__ Tables g_tab;
#define TAB_U64 ((int)(sizeof(Tables) / 8))     // 1254
#define MST_U64 (RPB * HP)                      // 5120
#define SM_U64  (TAB_U64 + MST_U64)             // 6374
#define SM_BYTES (SM_U64 * 8)                   // 50992

// ---------- packed f32x2 helpers (sm_103a) ----------
static __device__ __forceinline__ u64 pk2(float lo, float hi) {
    u64 r; asm("mov.b64 %0,{%1,%2};" : "=l"(r) : "f"(lo), "f"(hi)); return r;
}
static __device__ __forceinline__ void upk2(u64 v, float& lo, float& hi) {
    asm("mov.b64 {%0,%1},%2;" : "=f"(lo), "=f"(hi) : "l"(v));
}
static __device__ __forceinline__ u64 fma2(u64 a, u64 b, u64 c) {
    u64 d; asm("fma.rn.f32x2 %0,%1,%2,%3;" : "=l"(d) : "l"(a), "l"(b), "l"(c)); return d;
}
static __device__ __forceinline__ float tanha(float v) {
    float r; asm("tanh.approx.f32 %0,%1;" : "=f"(r) : "f"(v)); return r;
}

// ---------- kernel 1: per-block partial sums of |x| ----------
__global__ void __launch_bounds__(256) k_partial(const float4* __restrict__ x, int n4) {
    float s = 0.f;
    for (int i = blockIdx.x * blockDim.x + threadIdx.x; i < n4;
         i += gridDim.x * blockDim.x) {
        float4 v = x[i];
        s += fabsf(v.x) + fabsf(v.y) + fabsf(v.z) + fabsf(v.w);
    }
#pragma unroll
    for (int o = 16; o > 0; o >>= 1) s += __shfl_down_sync(0xffffffffu, s, o);
    __shared__ float ws[8];
    int w = threadIdx.x >> 5, l = threadIdx.x & 31;
    if (l == 0) ws[w] = s;
    __syncthreads();
    if (threadIdx.x == 0) {
        float t = 0.f;
#pragma unroll
        for (int i = 0; i < 8; i++) t += ws[i];
        g_partials[blockIdx.x] = t;
    }
}

// ---------- kernel 2: finish reduction + build all packed tables ----------
__global__ void __launch_bounds__(256) k_prep(
    const float* __restrict__ Wi, const float* __restrict__ bi,
    const float* __restrict__ Wr, const float* __restrict__ Wo,
    const float* __restrict__ bo, const float* __restrict__ tau,
    const float* __restrict__ ta, float invN)
{
    __shared__ float red[256];
    __shared__ float urg_s;
    int t = threadIdx.x;

    float s = 0.f;
    for (int i = t; i < NPART; i += 256) s += g_partials[i];
    red[t] = s;
    __syncthreads();
#pragma unroll
    for (int o = 128; o > 0; o >>= 1) {
        if (t < o) red[t] += red[t + o];
        __syncthreads();
    }
    if (t == 0) urg_s = fmaxf(red[0] * invN, 0.01f);
    __syncthreads();
    float urg = urg_s;

    for (int i = t; i < DD * HP; i += 256) {
        int k = i / HP, jp = i % HP;
        float w0 = Wi[(2 * jp) * DD + k];
        float w1 = (2 * jp + 1 < HD) ? Wi[(2 * jp + 1) * DD + k] : 0.f;
        g_tab.Wi2[k * WPAD + jp] = pk2(w0, w1);
        if (jp == 0) {   // zero the pad slots
            g_tab.Wi2[k * WPAD + 10] = 0ull;
            g_tab.Wi2[k * WPAD + 11] = 0ull;
        }
    }
    for (int i = t; i < HD * HP; i += 256) {
        int k = i / HP, jp = i % HP;
        float r0 = Wr[(2 * jp) * HD + k];
        float r1 = (2 * jp + 1 < HD) ? Wr[(2 * jp + 1) * HD + k] : 0.f;
        g_tab.Wr2[k * WPAD + jp] = pk2(r0, r1);
        float o0 = Wo[(2 * jp) * HD + k];
        float o1 = (2 * jp + 1 < HD) ? Wo[(2 * jp + 1) * HD + k] : 0.f;
        g_tab.Wo2[k * WPAD + jp] = pk2(o0, o1);
        if (jp == 0) {
            g_tab.Wr2[k * WPAD + 10] = 0ull; g_tab.Wr2[k * WPAD + 11] = 0ull;
            g_tab.Wo2[k * WPAD + 10] = 0ull; g_tab.Wo2[k * WPAD + 11] = 0ull;
        }
    }
    if (t < HP) {
        float b0 = bi[2 * t];
        float b1 = (2 * t + 1 < HD) ? bi[2 * t + 1] : 0.f;
        g_tab.bi2[t] = pk2(b0, b1);
        float c0 = bo[2 * t];
        float c1 = (2 * t + 1 < HD) ? bo[2 * t + 1] : 0.f;
        g_tab.bo2[t] = pk2(c0, c1);

        float bd0, bd1 = 0.f;
        {
            float td = tau[2 * t] * (1.0f - ta[2 * t]) + ta[2 * t] / urg;
            td = fminf(fmaxf(td, 0.01f), 10.0f);
            bd0 = 0.01f / td;
        }
        if (2 * t + 1 < HD) {
            float td = tau[2 * t + 1] * (1.0f - ta[2 * t + 1]) + ta[2 * t + 1] / urg;
            td = fminf(fmaxf(td, 0.01f), 10.0f);
            bd1 = 0.01f / td;
        }
        g_tab.bdt2[t] = pk2(bd0, bd1);
    }
}

// ---------- kernel 3: fused mapped + recurrence + output, 4 rows/thread ----------
__global__ void __launch_bounds__(TPB)
k_main(const float* __restrict__ x, const int* __restrict__ steps_p,
       float* __restrict__ out, float* __restrict__ hout)
{
    extern __shared__ __align__(16) u64 sm[];   // SM_BYTES
    const int tid = threadIdx.x;

    {   // stage tables
        const u64* gt = (const u64*)&g_tab;
        for (int i = tid; i < TAB_U64; i += TPB) sm[i] = gt[i];
    }
    __syncthreads();
    const u64* sWi = sm;                        // @0     (768)
    const u64* sWr = sWi + DD * WPAD;           // @768   (228)
    const u64* sWo = sWr + HD * WPAD;           // @996   (228)
    const u64* sBi = sWo + HD * WPAD;           // @1224  (10)
    const u64* sBo = sBi + HP;                  // @1234  (10)
    const u64* sBd = sBo + HP;                  // @1244  (10)
    u64* mst = sm + TAB_U64;                    // @1254  (5120)
    // mstage layout: mst[(p*RPT + r)*TPB + tid]

    // ---- phase 1: mapped = x @ Wi^T + bi, per row sequentially ----
    for (int r = 0; r < RPT; r++) {
        const float4* xr = (const float4*)(x +
            ((size_t)blockIdx.x * RPB + r * TPB + tid) * DD);
        u64 m[HP];
#pragma unroll
        for (int p = 0; p < HP; p++) m[p] = sBi[p];
#pragma unroll 4
        for (int q = 0; q < DD / 4; q++) {
            float4 v = xr[q];
            float vv[4] = {v.x, v.y, v.z, v.w};
#pragma unroll
            for (int e = 0; e < 4; e++) {
                u64 xd = pk2(vv[e], vv[e]);
                const u64x2* w = (const u64x2*)&sWi[(q * 4 + e) * WPAD];
#pragma unroll
                for (int p5 = 0; p5 < 5; p5++) {
                    u64x2 ww = w[p5];
                    m[2 * p5]     = fma2(xd, ww.x, m[2 * p5]);
                    m[2 * p5 + 1] = fma2(xd, ww.y, m[2 * p5 + 1]);
                }
            }
        }
#pragma unroll
        for (int p = 0; p < HP; p++) mst[(p * RPT + r) * TPB + tid] = m[p];
    }
    __syncthreads();

    // ---- phase 2: recurrence, 4 rows, h packed over hidden pairs ----
    u64 h[RPT][HP];
    const u64 zero2 = pk2(0.f, 0.f);
    const u64 neg1  = pk2(-1.f, -1.f);
#pragma unroll
    for (int r = 0; r < RPT; r++)
#pragma unroll
        for (int p = 0; p < HP; p++) h[r][p] = zero2;

    const int steps = *steps_p;
    for (int s = 0; s < steps; s++) {
        u64 a[RPT][HP];
#pragma unroll
        for (int p = 0; p < HP; p++)
#pragma unroll
            for (int r = 0; r < RPT; r++)
                a[r][p] = mst[(p * RPT + r) * TPB + tid];

#pragma unroll
        for (int k = 0; k < HD; k++) {
            // broadcast h[.][k] into dup pairs
            u64 d[RPT];
#pragma unroll
            for (int r = 0; r < RPT; r++) {
                float lo, hi;
                upk2(h[r][k >> 1], lo, hi);
                float hv = (k & 1) ? hi : lo;
                d[r] = pk2(hv, hv);
            }
            const u64x2* w = (const u64x2*)&sWr[k * WPAD];
#pragma unroll
            for (int p5 = 0; p5 < 5; p5++) {
                u64x2 ww = w[p5];
#pragma unroll
                for (int r = 0; r < RPT; r++) {
                    a[r][2 * p5]     = fma2(d[r], ww.x, a[r][2 * p5]);
                    a[r][2 * p5 + 1] = fma2(d[r], ww.y, a[r][2 * p5 + 1]);
                }
            }
        }

        // h += b * (tanh(a) - h); b reloaded from smem (broadcast)
#pragma unroll
        for (int p = 0; p < HP; p++) {
            u64 bbp = sBd[p];
#pragma unroll
            for (int r = 0; r < RPT; r++) {
                float u, v;
                upk2(a[r][p], u, v);
                u64 act = pk2(tanha(u), tanha(v));
                u64 dlt = fma2(h[r][p], neg1, act);
                h[r][p] = fma2(bbp, dlt, h[r][p]);
            }
        }
    }

    // ---- phase 3a: out = h @ Wo^T + bo, stage + store ----
    __syncthreads();                 // tables Wi region reused? no — mst reused
    float* f = (float*)mst;          // 10240 floats available, need 9728
    for (int r = 0; r < RPT; r++) {
        u64 o[HP];
#pragma unroll
        for (int p = 0; p < HP; p++) o[p] = sBo[p];
#pragma unroll
        for (int k = 0; k < HD; k++) {
            float lo, hi;
            upk2(h[r][k >> 1], lo, hi);
            float hv = (k & 1) ? hi : lo;
            u64 dk = pk2(hv, hv);
            const u64x2* w = (const u64x2*)&sWo[k * WPAD];
#pragma unroll
            for (int p5 = 0; p5 < 5; p5++) {
                u64x2 ww = w[p5];
                o[2 * p5]     = fma2(dk, ww.x, o[2 * p5]);
                o[2 * p5 + 1] = fma2(dk, ww.y, o[2 * p5 + 1]);
            }
        }
        const int base = (r * TPB + tid) * HD;
#pragma unroll
        for (int p = 0; p < HP; p++) {
            float lo, hi;
            upk2(o[p], lo, hi);
            f[base + 2 * p] = lo;
            if (p < HP - 1) f[base + 2 * p + 1] = hi;
        }
    }
    __syncthreads();
    {
        float4* go = (float4*)(out + (size_t)blockIdx.x * (RPB * HD));
        const float4* f4 = (const float4*)f;
        for (int i = tid; i < RPB * HD / 4; i += TPB) go[i] = f4[i];
    }

    // ---- phase 3b: stage + store h ----
    if (hout) {
        __syncthreads();
        for (int r = 0; r < RPT; r++) {
            const int base = (r * TPB + tid) * HD;
#pragma unroll
            for (int p = 0; p < HP; p++) {
                float lo, hi;
                upk2(h[r][p], lo, hi);
                f[base + 2 * p] = lo;
                if (p < HP - 1) f[base + 2 * p + 1] = hi;
            }
        }
        __syncthreads();
        float4* gh = (float4*)(hout + (size_t)blockIdx.x * (RPB * HD));
        const float4* f4 = (const float4*)f;
        for (int i = tid; i < RPB * HD / 4; i += TPB) gh[i] = f4[i];
    }
}

extern "C" void kernel_launch(void* const* d_in, const int* in_sizes, int n_in,
                              void* d_out, int out_size) {
    const float* x   = (const float*)d_in[0];
    const float* Wi  = (const float*)d_in[1];
    const float* bi  = (const float*)d_in[2];
    const float* Wr  = (const float*)d_in[3];
    const float* Wo  = (const float*)d_in[4];
    const float* bo  = (const float*)d_in[5];
    const float* tau = (const float*)d_in[6];
    const float* ta  = (const float*)d_in[7];
    const int* steps = (const int*)d_in[8];

    const int nx = in_sizes[0];
    const int B  = nx / DD;

    float* out = (float*)d_out;
    long long bh = (long long)B * HD;
    float* hout = ((long long)out_size >= 2 * bh) ? (out + bh) : nullptr;

    static int smem_set = 0;
    if (!smem_set) {
        cudaFuncSetAttribute(k_main, cudaFuncAttributeMaxDynamicSharedMemorySize,
                             SM_BYTES);
        smem_set = 1;
    }

    k_partial<<<NPART, 256>>>((const float4*)x, nx / 4);
    k_prep<<<1, 256>>>(Wi, bi, Wr, Wo, bo, tau, ta, 1.0f / (float)nx);
    k_main<<<B / RPB, TPB, SM_BYTES>>>(x, steps, out, hout);
}